// round 1
// baseline (speedup 1.0000x reference)
#include <cuda_runtime.h>
#include <math.h>

// ---------------------------------------------------------------------------
// SSIM loss, fused single-pass:
//   per 32x32 tile: load 42x42 halo of img1/img2 -> smem
//   horizontal 11-tap Gaussian on 5 channels (x1, x2, x1^2, x2^2, x1*x2)
//   vertical 11-tap Gaussian + SSIM map + clip + block reduction
//   atomicAdd(double) into global accumulator; finalize kernel -> 1 - mean
// ---------------------------------------------------------------------------

#define IMGW 512
#define IMGH 512
#define TW   32
#define TH   32
#define HALO 5
#define HW   (TW + 2*HALO)   // 42
#define HR   (TH + 2*HALO)   // 42
#define NTHREADS 256

__device__ double g_acc;
__device__ float  g_w[11];

__global__ void ssim_init_kernel() {
    if (threadIdx.x == 0) {
        g_acc = 0.0;
        float g[11];
        float s = 0.0f;
        for (int i = 0; i < 11; i++) {
            float d = (float)(i - 5);
            g[i] = expf(-d * d / 4.5f);   // 2*sigma^2 = 4.5
            s += g[i];
        }
        for (int i = 0; i < 11; i++) g_w[i] = g[i] / s;
    }
}

__device__ __forceinline__ int reflect_idx(int i, int n) {
    if (i < 0) i = -i;
    if (i >= n) i = 2 * n - 2 - i;
    return i;
}

__global__ __launch_bounds__(NTHREADS)
void ssim_main_kernel(const float* __restrict__ img1,
                      const float* __restrict__ img2) {
    __shared__ float s1[HR * HW];
    __shared__ float s2[HR * HW];
    __shared__ float hb[5][HR * TW];
    __shared__ float warpsum[NTHREADS / 32];

    const int tid = threadIdx.x;
    const int img = blockIdx.z;
    const int tx0 = blockIdx.x * TW;
    const int ty0 = blockIdx.y * TH;

    const float* a = img1 + (size_t)img * (IMGW * IMGH);
    const float* b = img2 + (size_t)img * (IMGW * IMGH);

    // weights (L1/L2-cached global reads)
    float w[11];
#pragma unroll
    for (int i = 0; i < 11; i++) w[i] = g_w[i];

    // ---- load halo tile (reflect padding) ----
    for (int idx = tid; idx < HR * HW; idx += NTHREADS) {
        int r = idx / HW;
        int c = idx - r * HW;
        int gy = reflect_idx(ty0 + r - HALO, IMGH);
        int gx = reflect_idx(tx0 + c - HALO, IMGW);
        s1[idx] = a[gy * IMGW + gx];
        s2[idx] = b[gy * IMGW + gx];
    }
    __syncthreads();

    // ---- horizontal pass: 5 channels, 4-col register sliding window ----
    // tasks: HR rows x (TW/4) col-groups = 42*8 = 336
    for (int task = tid; task < HR * (TW / 4); task += NTHREADS) {
        int r  = task >> 3;
        int c0 = (task & 7) << 2;
        const float* p1 = s1 + r * HW + c0;
        const float* p2 = s2 + r * HW + c0;
        float va[14], vb[14];
#pragma unroll
        for (int i = 0; i < 14; i++) { va[i] = p1[i]; vb[i] = p2[i]; }

        float v1[4]  = {0.f, 0.f, 0.f, 0.f};
        float v2[4]  = {0.f, 0.f, 0.f, 0.f};
        float v11[4] = {0.f, 0.f, 0.f, 0.f};
        float v22[4] = {0.f, 0.f, 0.f, 0.f};
        float v12[4] = {0.f, 0.f, 0.f, 0.f};
#pragma unroll
        for (int k = 0; k < 11; k++) {
            float wk = w[k];
#pragma unroll
            for (int j = 0; j < 4; j++) {
                float av = va[j + k];
                float bv = vb[j + k];
                float wa = wk * av;
                float wb = wk * bv;
                v1[j]  += wa;
                v2[j]  += wb;
                v11[j] = fmaf(wa, av, v11[j]);
                v22[j] = fmaf(wb, bv, v22[j]);
                v12[j] = fmaf(wa, bv, v12[j]);
            }
        }
        int o = r * TW + c0;
        *(float4*)&hb[0][o] = make_float4(v1[0],  v1[1],  v1[2],  v1[3]);
        *(float4*)&hb[1][o] = make_float4(v2[0],  v2[1],  v2[2],  v2[3]);
        *(float4*)&hb[2][o] = make_float4(v11[0], v11[1], v11[2], v11[3]);
        *(float4*)&hb[3][o] = make_float4(v22[0], v22[1], v22[2], v22[3]);
        *(float4*)&hb[4][o] = make_float4(v12[0], v12[1], v12[2], v12[3]);
    }
    __syncthreads();

    // ---- vertical pass + SSIM: thread = (col, 4-row strip) ----
    const int tx = tid & 31;          // column 0..31
    const int r0 = (tid >> 5) << 2;   // row base 0,4,...,28

    float m[5][4];
#pragma unroll
    for (int c = 0; c < 5; c++) {
        float acc0 = 0.f, acc1 = 0.f, acc2 = 0.f, acc3 = 0.f;
#pragma unroll
        for (int k = 0; k < 14; k++) {
            float hv = hb[c][(r0 + k) * TW + tx];
            if (k <= 10)           acc0 = fmaf(w[k],     hv, acc0);
            if (k >= 1 && k <= 11) acc1 = fmaf(w[k - 1], hv, acc1);
            if (k >= 2 && k <= 12) acc2 = fmaf(w[k - 2], hv, acc2);
            if (k >= 3)            acc3 = fmaf(w[k - 3], hv, acc3);
        }
        m[c][0] = acc0; m[c][1] = acc1; m[c][2] = acc2; m[c][3] = acc3;
    }

    const float C1 = 1e-4f;   // (0.01*1.0)^2
    const float C2 = 9e-4f;   // (0.03*1.0)^2
    float lsum = 0.f;
#pragma unroll
    for (int j = 0; j < 4; j++) {
        float mu1 = m[0][j], mu2 = m[1][j];
        float e11 = m[2][j], e22 = m[3][j], e12 = m[4][j];
        float mu1sq = mu1 * mu1;
        float mu2sq = mu2 * mu2;
        float mu12  = mu1 * mu2;
        float sg1 = e11 - mu1sq;
        float sg2 = e22 - mu2sq;
        float sg12 = e12 - mu12;
        float num = fmaf(2.f, mu12, C1) * fmaf(2.f, sg12, C2);
        float den = (mu1sq + mu2sq + C1) * (sg1 + sg2 + C2);
        float v = __fdividef(num, den);
        v = fminf(fmaxf(v, 0.f), 1.f);
        lsum += v;
    }

    // ---- block reduction ----
#pragma unroll
    for (int off = 16; off > 0; off >>= 1)
        lsum += __shfl_xor_sync(0xffffffff, lsum, off);
    if ((tid & 31) == 0) warpsum[tid >> 5] = lsum;
    __syncthreads();
    if (tid == 0) {
        double s = 0.0;
#pragma unroll
        for (int i = 0; i < NTHREADS / 32; i++) s += (double)warpsum[i];
        atomicAdd(&g_acc, s);
    }
}

__global__ void ssim_final_kernel(float* out) {
    if (threadIdx.x == 0) {
        const double npix = 16.0 * 3.0 * 512.0 * 512.0;
        out[0] = (float)(1.0 - g_acc / npix);
    }
}

extern "C" void kernel_launch(void* const* d_in, const int* in_sizes, int n_in,
                              void* d_out, int out_size) {
    const float* img1 = (const float*)d_in[0];
    const float* img2 = (const float*)d_in[1];
    float* out = (float*)d_out;

    ssim_init_kernel<<<1, 32>>>();
    dim3 grid(IMGW / TW, IMGH / TH, 16 * 3);
    ssim_main_kernel<<<grid, NTHREADS>>>(img1, img2);
    ssim_final_kernel<<<1, 32>>>(out);
}

// round 2
// speedup vs baseline: 1.1037x; 1.1037x over previous
#include <cuda_runtime.h>

// ---------------------------------------------------------------------------
// SSIM loss, fused single-pass, FFMA-imm optimized:
//   - Gaussian weights hardcoded as float literals -> ptxas emits
//     FFMA R,R,IMM,R (rt_SMSP=1, 2x throughput of 3-reg FFMA on sm_103a)
//   - horizontal pass precomputes a^2, b^2, a*b once per halo element so all
//     5 channels are single imm-FFMA chains
// ---------------------------------------------------------------------------

#define IMGW 512
#define IMGH 512
#define TW   32
#define TH   32
#define HALO 5
#define HW   (TW + 2*HALO)   // 42
#define HR   (TH + 2*HALO)   // 42
#define NTHREADS 256

// Normalized 11-tap Gaussian, sigma=1.5 (exp(-d^2/4.5)/sum), double-precision
// derived, accurate to ~1e-7 vs the fp32 reference weights.
__device__ __constant__ const float kW[11] = {
    0.00102838f, 0.00759876f, 0.03600077f, 0.10936069f, 0.21300554f,
    0.26601173f,
    0.21300554f, 0.10936069f, 0.03600077f, 0.00759876f, 0.00102838f
};
// Compile-time copies as literals (constexpr so indices fold to immediates)
#define W0 0.00102838f
#define W1 0.00759876f
#define W2 0.03600077f
#define W3 0.10936069f
#define W4 0.21300554f
#define W5 0.26601173f

__device__ double g_acc;

__global__ void ssim_init_kernel() {
    if (threadIdx.x == 0) g_acc = 0.0;
}

__device__ __forceinline__ int reflect_idx(int i, int n) {
    if (i < 0) i = -i;
    if (i >= n) i = 2 * n - 2 - i;
    return i;
}

// weight by tap index as a compile-time constant expression
__device__ __forceinline__ constexpr float WT(int k) {
    return (k == 0 || k == 10) ? W0
         : (k == 1 || k == 9)  ? W1
         : (k == 2 || k == 8)  ? W2
         : (k == 3 || k == 7)  ? W3
         : (k == 4 || k == 6)  ? W4
         : W5;
}

__global__ __launch_bounds__(NTHREADS)
void ssim_main_kernel(const float* __restrict__ img1,
                      const float* __restrict__ img2) {
    __shared__ float s1[HR * HW];
    __shared__ float s2[HR * HW];
    __shared__ float hb[5][HR * TW];
    __shared__ float warpsum[NTHREADS / 32];

    const int tid = threadIdx.x;
    const int img = blockIdx.z;
    const int tx0 = blockIdx.x * TW;
    const int ty0 = blockIdx.y * TH;

    const float* a = img1 + (size_t)img * (IMGW * IMGH);
    const float* b = img2 + (size_t)img * (IMGW * IMGH);

    // ---- load halo tile (reflect padding) ----
    for (int idx = tid; idx < HR * HW; idx += NTHREADS) {
        int r = idx / HW;
        int c = idx - r * HW;
        int gy = reflect_idx(ty0 + r - HALO, IMGH);
        int gx = reflect_idx(tx0 + c - HALO, IMGW);
        s1[idx] = a[gy * IMGW + gx];
        s2[idx] = b[gy * IMGW + gx];
    }
    __syncthreads();

    // ---- horizontal pass: 5 channels, 4 outputs per task, imm-FFMA taps ----
    // tasks: HR rows x (TW/4) col-groups = 42*8 = 336
    for (int task = tid; task < HR * (TW / 4); task += NTHREADS) {
        int r  = task >> 3;
        int c0 = (task & 7) << 2;
        const float* p1 = s1 + r * HW + c0;
        const float* p2 = s2 + r * HW + c0;

        float va[14], vb[14], aa[14], bb[14], ab[14];
#pragma unroll
        for (int i = 0; i < 14; i++) {
            float av = p1[i];
            float bv = p2[i];
            va[i] = av; vb[i] = bv;
            aa[i] = av * av;
            bb[i] = bv * bv;
            ab[i] = av * bv;
        }

        float v1[4]  = {0.f, 0.f, 0.f, 0.f};
        float v2[4]  = {0.f, 0.f, 0.f, 0.f};
        float v11[4] = {0.f, 0.f, 0.f, 0.f};
        float v22[4] = {0.f, 0.f, 0.f, 0.f};
        float v12[4] = {0.f, 0.f, 0.f, 0.f};
#pragma unroll
        for (int k = 0; k < 11; k++) {
            const float wk = WT(k);   // compile-time literal -> FFMA-imm
#pragma unroll
            for (int j = 0; j < 4; j++) {
                v1[j]  = fmaf(wk, va[j + k], v1[j]);
                v2[j]  = fmaf(wk, vb[j + k], v2[j]);
                v11[j] = fmaf(wk, aa[j + k], v11[j]);
                v22[j] = fmaf(wk, bb[j + k], v22[j]);
                v12[j] = fmaf(wk, ab[j + k], v12[j]);
            }
        }
        int o = r * TW + c0;
        *(float4*)&hb[0][o] = make_float4(v1[0],  v1[1],  v1[2],  v1[3]);
        *(float4*)&hb[1][o] = make_float4(v2[0],  v2[1],  v2[2],  v2[3]);
        *(float4*)&hb[2][o] = make_float4(v11[0], v11[1], v11[2], v11[3]);
        *(float4*)&hb[3][o] = make_float4(v22[0], v22[1], v22[2], v22[3]);
        *(float4*)&hb[4][o] = make_float4(v12[0], v12[1], v12[2], v12[3]);
    }
    __syncthreads();

    // ---- vertical pass + SSIM: thread = (col, 4-row strip) ----
    const int tx = tid & 31;          // column 0..31
    const int r0 = (tid >> 5) << 2;   // row base 0,4,...,28

    float m[5][4];
#pragma unroll
    for (int c = 0; c < 5; c++) {
        float acc0 = 0.f, acc1 = 0.f, acc2 = 0.f, acc3 = 0.f;
#pragma unroll
        for (int k = 0; k < 14; k++) {
            float hv = hb[c][(r0 + k) * TW + tx];
            if (k <= 10)           acc0 = fmaf(WT(k),     hv, acc0);
            if (k >= 1 && k <= 11) acc1 = fmaf(WT(k - 1), hv, acc1);
            if (k >= 2 && k <= 12) acc2 = fmaf(WT(k - 2), hv, acc2);
            if (k >= 3)            acc3 = fmaf(WT(k - 3), hv, acc3);
        }
        m[c][0] = acc0; m[c][1] = acc1; m[c][2] = acc2; m[c][3] = acc3;
    }

    const float C1 = 1e-4f;   // (0.01*1.0)^2
    const float C2 = 9e-4f;   // (0.03*1.0)^2
    float lsum = 0.f;
#pragma unroll
    for (int j = 0; j < 4; j++) {
        float mu1 = m[0][j], mu2 = m[1][j];
        float e11 = m[2][j], e22 = m[3][j], e12 = m[4][j];
        float mu1sq = mu1 * mu1;
        float mu2sq = mu2 * mu2;
        float mu12  = mu1 * mu2;
        float sg1 = e11 - mu1sq;
        float sg2 = e22 - mu2sq;
        float sg12 = e12 - mu12;
        float num = fmaf(2.f, mu12, C1) * fmaf(2.f, sg12, C2);
        float den = (mu1sq + mu2sq + C1) * (sg1 + sg2 + C2);
        float v = __fdividef(num, den);
        v = fminf(fmaxf(v, 0.f), 1.f);
        lsum += v;
    }

    // ---- block reduction ----
#pragma unroll
    for (int off = 16; off > 0; off >>= 1)
        lsum += __shfl_xor_sync(0xffffffff, lsum, off);
    if ((tid & 31) == 0) warpsum[tid >> 5] = lsum;
    __syncthreads();
    if (tid == 0) {
        double s = 0.0;
#pragma unroll
        for (int i = 0; i < NTHREADS / 32; i++) s += (double)warpsum[i];
        atomicAdd(&g_acc, s);
    }
}

__global__ void ssim_final_kernel(float* out) {
    if (threadIdx.x == 0) {
        const double npix = 16.0 * 3.0 * 512.0 * 512.0;
        out[0] = (float)(1.0 - g_acc / npix);
    }
}

extern "C" void kernel_launch(void* const* d_in, const int* in_sizes, int n_in,
                              void* d_out, int out_size) {
    const float* img1 = (const float*)d_in[0];
    const float* img2 = (const float*)d_in[1];
    float* out = (float*)d_out;

    ssim_init_kernel<<<1, 32>>>();
    dim3 grid(IMGW / TW, IMGH / TH, 16 * 3);
    ssim_main_kernel<<<grid, NTHREADS>>>(img1, img2);
    ssim_final_kernel<<<1, 32>>>(out);
}